// round 5
// baseline (speedup 1.0000x reference)
#include <cuda_runtime.h>

// Problem constants
#define H_IMG 200
#define W_IMG 176
#define CIN   256
#define PCH   28
#define BATCH 4
#define NBOX  2048
#define TILE_X 64
#define TILE_Y 4
#define CC     4      // input channels per smem chunk

// Scratch (device globals — no allocation allowed)
__device__ float g_feat2[(size_t)BATCH * PCH * H_IMG * W_IMG];  // conv2 output planes
__device__ float g_wt[CIN * 9 * PCH];                           // conv1 w, BN-scale folded, [c][tap][p]
__device__ float g_shift[PCH];                                  // BN shift (bias)

// ---------- packed f32x2 helpers ----------
__device__ __forceinline__ unsigned long long pack2(float lo, float hi) {
    unsigned long long r;
    asm("mov.b64 %0, {%1,%2};" : "=l"(r) : "f"(lo), "f"(hi));
    return r;
}
__device__ __forceinline__ void unpack2(unsigned long long v, float& lo, float& hi) {
    asm("mov.b64 {%0,%1}, %2;" : "=f"(lo), "=f"(hi) : "l"(v));
}
__device__ __forceinline__ void ffma2(unsigned long long& d, unsigned long long a, unsigned long long b) {
    // d = a * b + d  (elementwise on 2 packed fp32)
    asm("fma.rn.f32x2 %0, %1, %2, %0;" : "+l"(d) : "l"(a), "l"(b));
}

// ---------- prep: fold BN scale into conv1 weights, transpose to [c][tap][p] ----------
__global__ void prep_kernel(const float* __restrict__ w1,
                            const float* __restrict__ gamma,
                            const float* __restrict__ beta,
                            const float* __restrict__ mean,
                            const float* __restrict__ var) {
    int idx = blockIdx.x * blockDim.x + threadIdx.x;
    if (idx < PCH) {
        float inv = gamma[idx] * rsqrtf(var[idx] + 1e-3f);
        g_shift[idx] = beta[idx] - mean[idx] * inv;
    }
    if (idx < CIN * 9 * PCH) {
        int c   = idx / (9 * PCH);
        int rem = idx % (9 * PCH);
        int kk  = rem / PCH;
        int p   = rem % PCH;
        float sc = gamma[p] * rsqrtf(var[p] + 1e-3f);
        g_wt[idx] = w1[(p * CIN + c) * 9 + kk] * sc;
    }
}

// ---------- fused conv1(3x3) + BN + ReLU + conv2(1x1) ----------
// Block: 128 threads = (tx:8) x (ty:4) x (tp:4). Tile: 64x * 4y pixels, all 28 channels.
// Thread register tile: 7 output channels x 8 pixels (as 4 f32x2 pairs) = 28 u64 accumulators.
__global__ __launch_bounds__(128) void conv_kernel(const float* __restrict__ x,
                                                   const float* __restrict__ w2) {
    __shared__ float xs[CC][6][67];           // input tile + 3x3 halo, odd stride (2-way max conflicts)
    __shared__ float ws[CC][9][PCH];          // folded conv1 weights for this chunk (warp-broadcast reads)
    __shared__ float relu_s[TILE_X * TILE_Y][29];  // pixel-major, stride 29 => conflict-free
    __shared__ float w2s[PCH * PCH];

    const int tid = threadIdx.x;
    const int tx = tid & 7;
    const int ty = (tid >> 3) & 3;
    const int tp = tid >> 5;
    const int x0 = blockIdx.x * TILE_X;
    const int y0 = blockIdx.y * TILE_Y;
    const int b  = blockIdx.z;

    for (int k = tid; k < PCH * PCH; k += 128) w2s[k] = w2[k];

    // accumulators init with BN shift (scale already folded into weights)
    unsigned long long acc[7][4];
#pragma unroll
    for (int i = 0; i < 7; i++) {
        float sh = g_shift[tp * 7 + i];
        unsigned long long s2 = pack2(sh, sh);
#pragma unroll
        for (int m = 0; m < 4; m++) acc[i][m] = s2;
    }

    const float* xb = x + (size_t)b * CIN * H_IMG * W_IMG;

    for (int c0 = 0; c0 < CIN; c0 += CC) {
        __syncthreads();
        // stage input tile (with zero halo = SAME padding)
        for (int k = tid; k < CC * 6 * 66; k += 128) {
            int c   = k / (6 * 66);
            int r   = (k / 66) % 6;
            int col = k % 66;
            int gy = y0 - 1 + r;
            int gx = x0 - 1 + col;
            float v = 0.f;
            if (gy >= 0 && gy < H_IMG && gx >= 0 && gx < W_IMG)
                v = xb[(size_t)(c0 + c) * (H_IMG * W_IMG) + gy * W_IMG + gx];
            xs[c][r][col] = v;
        }
        // stage weights (contiguous thanks to prep transpose)
        for (int k = tid; k < CC * 9 * PCH; k += 128)
            ((float*)ws)[k] = g_wt[c0 * 9 * PCH + k];
        __syncthreads();

#pragma unroll
        for (int c = 0; c < CC; c++) {
#pragma unroll
            for (int ky = 0; ky < 3; ky++) {
                float v[10];
                const float* row = &xs[c][ty + ky][tx * 8];
#pragma unroll
                for (int j = 0; j < 10; j++) v[j] = row[j];
                unsigned long long pe[5], po[4];
#pragma unroll
                for (int m = 0; m < 5; m++) pe[m] = pack2(v[2 * m], v[2 * m + 1]);
#pragma unroll
                for (int m = 0; m < 4; m++) po[m] = pack2(v[2 * m + 1], v[2 * m + 2]);
#pragma unroll
                for (int kx = 0; kx < 3; kx++) {
                    unsigned long long wp[7];
#pragma unroll
                    for (int i = 0; i < 7; i++) {
                        float w = ws[c][ky * 3 + kx][tp * 7 + i];
                        wp[i] = pack2(w, w);
                    }
#pragma unroll
                    for (int i = 0; i < 7; i++) {
#pragma unroll
                        for (int m = 0; m < 4; m++) {
                            unsigned long long xv = (kx == 0) ? pe[m] : (kx == 1) ? po[m] : pe[m + 1];
                            ffma2(acc[i][m], wp[i], xv);
                        }
                    }
                }
            }
        }
    }

    // ReLU -> shared (pixel-major)
#pragma unroll
    for (int i = 0; i < 7; i++) {
#pragma unroll
        for (int m = 0; m < 4; m++) {
            float a, bb;
            unpack2(acc[i][m], a, bb);
            a  = fmaxf(a, 0.f);
            bb = fmaxf(bb, 0.f);
            int pix = ty * 64 + tx * 8 + 2 * m;
            relu_s[pix][tp * 7 + i]     = a;
            relu_s[pix + 1][tp * 7 + i] = bb;
        }
    }
    __syncthreads();

    // fused 1x1 conv2 + store feat2
#pragma unroll
    for (int i = 0; i < 7; i++) {
        int pout = tp * 7 + i;
        float o[8];
#pragma unroll
        for (int k = 0; k < 8; k++) o[k] = 0.f;
#pragma unroll
        for (int q = 0; q < PCH; q++) {
            float w = w2s[pout * PCH + q];
#pragma unroll
            for (int k = 0; k < 8; k++)
                o[k] = fmaf(w, relu_s[ty * 64 + tx * 8 + k][q], o[k]);
        }
        int px = x0 + tx * 8;
        float* dst = g_feat2 + (((size_t)b * PCH + pout) * H_IMG + (y0 + ty)) * W_IMG + px;
#pragma unroll
        for (int k = 0; k < 8; k++)
            if (px + k < W_IMG) dst[k] = o[k];
    }
}

// ---------- rotated position-sensitive sampling: one warp per box ----------
__global__ void sample_kernel(const float* __restrict__ boxes, float* __restrict__ out) {
    int gwarp = (blockIdx.x * blockDim.x + threadIdx.x) >> 5;
    int lane  = threadIdx.x & 31;
    if (gwarp >= BATCH * NBOX) return;
    int b = gwarp >> 11;           // / 2048
    int n = gwarp & (NBOX - 1);
    const float* bx = boxes + (size_t)(b * NBOX + n) * 7;

    float val = 0.f;
    if (lane < PCH) {
        float xg = bx[0], yg = bx[1], wg = bx[3], lg = bx[4], rg = bx[6];
        int i = lane / 7;            // WIN_H index
        int j = lane - i * 7;        // WIN_W index  (channel p == lane == i*7+j)
        float lx = (float)i * (1.f / 3.f) - 0.5f;
        float ly = (float)j * (1.f / 6.f) - 0.5f;
        float xx = lx * wg;
        float yy = ly * lg;
        float sT, cT;
        sincosf(rg, &sT, &cT);
        float gx = (xx * cT + yy * sT + xg) * 2.5f;           // GRID_OFF.x = 0, scale = 1/0.4
        float gy = (yy * cT - xx * sT + yg + 40.f) * 2.5f;    // GRID_OFF.y = 40

        const float* img = g_feat2 + ((size_t)b * PCH + lane) * (H_IMG * W_IMG);
        float xf = floorf(gx), yf = floorf(gy);
        int xi = (int)xf, yi = (int)yf;
        float fx = gx - xf, fy = gy - yf;
        float Ia = 0.f, Ib = 0.f, Ic = 0.f, Id = 0.f;
        bool vx0 = (xi >= 0) && (xi <= W_IMG - 1);
        bool vx1 = (xi + 1 >= 0) && (xi + 1 <= W_IMG - 1);
        bool vy0 = (yi >= 0) && (yi <= H_IMG - 1);
        bool vy1 = (yi + 1 >= 0) && (yi + 1 <= H_IMG - 1);
        if (vy0 && vx0) Ia = img[yi * W_IMG + xi];
        if (vy1 && vx0) Ib = img[(yi + 1) * W_IMG + xi];
        if (vy0 && vx1) Ic = img[yi * W_IMG + xi + 1];
        if (vy1 && vx1) Id = img[(yi + 1) * W_IMG + xi + 1];
        val = (1.f - fx) * (1.f - fy) * Ia + (1.f - fx) * fy * Ib
            + fx * (1.f - fy) * Ic + fx * fy * Id;
    }
#pragma unroll
    for (int off = 16; off; off >>= 1)
        val += __shfl_xor_sync(0xffffffffu, val, off);
    if (lane == 0) out[b * NBOX + n] = val * (1.f / 28.f);
}

// ---------- launch ----------
extern "C" void kernel_launch(void* const* d_in, const int* in_sizes, int n_in,
                              void* d_out, int out_size) {
    const float* x     = (const float*)d_in[0];
    const float* boxes = (const float*)d_in[1];
    const float* w1    = (const float*)d_in[2];
    const float* gamma = (const float*)d_in[3];
    const float* beta  = (const float*)d_in[4];
    const float* mean  = (const float*)d_in[5];
    const float* var   = (const float*)d_in[6];
    const float* w2    = (const float*)d_in[7];
    float* out = (float*)d_out;

    prep_kernel<<<252, 256>>>(w1, gamma, beta, mean, var);   // 252*256 == 256*9*28

    dim3 grid((W_IMG + TILE_X - 1) / TILE_X, H_IMG / TILE_Y, BATCH);  // (3, 50, 4)
    conv_kernel<<<grid, 128>>>(x, w2);

    sample_kernel<<<(BATCH * NBOX * 32) / 256, 256>>>(boxes, out);    // 1024 blocks
}

// round 6
// speedup vs baseline: 1.1357x; 1.1357x over previous
#include <cuda_runtime.h>

// Problem constants
#define H_IMG 200
#define W_IMG 176
#define CIN   256
#define PCH   28
#define BATCH 4
#define NBOX  2048
#define TILE_X 64
#define TILE_Y 4
#define CC     4      // input channels per smem chunk

#define XROW   75     // swizzled row stride (conflict-free, see analysis)
#define XS_FLOATS (CC * 6 * XROW)          // 1800
#define WS_FLOATS (CC * 9 * PCH * 2)       // 2016 (duplicated pairs)
#define RELU_FLOATS (TILE_X * TILE_Y * 32) // 8192

// Scratch (device globals — no allocation allowed)
__device__ float g_feat2[(size_t)BATCH * PCH * H_IMG * W_IMG];  // conv2 output planes
__device__ float g_wt2[CIN * 9 * PCH * 2];                      // conv1 w, BN folded, duplicated (w,w) pairs, [c][tap][p][2]
__device__ float g_shift[PCH];                                  // BN shift (bias)

// ---------- packed f32x2 helpers ----------
__device__ __forceinline__ unsigned long long pack2(float lo, float hi) {
    unsigned long long r;
    asm("mov.b64 %0, {%1,%2};" : "=l"(r) : "f"(lo), "f"(hi));
    return r;
}
__device__ __forceinline__ void unpack2(unsigned long long v, float& lo, float& hi) {
    asm("mov.b64 {%0,%1}, %2;" : "=f"(lo), "=f"(hi) : "l"(v));
}
__device__ __forceinline__ void ffma2(unsigned long long& d, unsigned long long a, unsigned long long b) {
    asm("fma.rn.f32x2 %0, %1, %2, %0;" : "+l"(d) : "l"(a), "l"(b));
}

// ---------- prep: fold BN scale into conv1 weights, transpose to [c][tap][p], duplicate pairs ----------
__global__ void prep_kernel(const float* __restrict__ w1,
                            const float* __restrict__ gamma,
                            const float* __restrict__ beta,
                            const float* __restrict__ mean,
                            const float* __restrict__ var) {
    int idx = blockIdx.x * blockDim.x + threadIdx.x;
    if (idx < PCH) {
        float inv = gamma[idx] * rsqrtf(var[idx] + 1e-3f);
        g_shift[idx] = beta[idx] - mean[idx] * inv;
    }
    if (idx < CIN * 9 * PCH) {
        int c   = idx / (9 * PCH);
        int rem = idx % (9 * PCH);
        int kk  = rem / PCH;
        int p   = rem % PCH;
        float sc = gamma[p] * rsqrtf(var[p] + 1e-3f);
        float v = w1[(p * CIN + c) * 9 + kk] * sc;
        g_wt2[2 * idx]     = v;
        g_wt2[2 * idx + 1] = v;
    }
}

// ---------- fused conv1(3x3) + BN + ReLU + conv2(1x1) ----------
// Block: 128 threads = (tx:8) x (ty:4) x (tp:4). Tile: 64x * 4y pixels, all 28 channels.
// Thread register tile: 7 output channels x 8 pixels (4 f32x2 pairs) = 28 u64 accumulators.
__global__ __launch_bounds__(128) void conv_kernel(const float* __restrict__ x,
                                                   const float* __restrict__ w2) {
    // Union: conv phase uses [xs | ws_dup]; epilogue reuses as relu buffer.
    __shared__ __align__(16) float buf[RELU_FLOATS];   // 32 KB (>= XS_FLOATS + WS_FLOATS)
    __shared__ float w2s[PCH * PCH];

    float* xs  = buf;                // CC x 6 x XROW, swizzled
    float* wsd = buf + XS_FLOATS;    // CC x 9 x PCH x 2 (duplicated weight pairs)

    const int tid = threadIdx.x;
    const int tx = tid & 7;
    const int ty = (tid >> 3) & 3;
    const int tp = tid >> 5;
    const int x0 = blockIdx.x * TILE_X;
    const int y0 = blockIdx.y * TILE_Y;
    const int b  = blockIdx.z;

    for (int k = tid; k < PCH * PCH; k += 128) w2s[k] = w2[k];

    // per-thread swizzled column offsets for the 10 input values
    int off[10];
#pragma unroll
    for (int j = 0; j < 10; j++) {
        int col = tx * 8 + j;
        off[j] = col + 4 * (col >> 5);
    }

    // accumulators init with BN shift (scale already folded into weights)
    unsigned long long acc[7][4];
#pragma unroll
    for (int i = 0; i < 7; i++) {
        float sh = g_shift[tp * 7 + i];
        unsigned long long s2 = pack2(sh, sh);
#pragma unroll
        for (int m = 0; m < 4; m++) acc[i][m] = s2;
    }

    const float* xb = x + (size_t)b * CIN * H_IMG * W_IMG;

    for (int c0 = 0; c0 < CIN; c0 += CC) {
        __syncthreads();
        // stage input tile (zero halo = SAME padding), swizzled store
        for (int k = tid; k < CC * 6 * 66; k += 128) {
            int c   = k / (6 * 66);
            int r   = (k / 66) % 6;
            int col = k % 66;
            int gy = y0 - 1 + r;
            int gx = x0 - 1 + col;
            float v = 0.f;
            if (gy >= 0 && gy < H_IMG && gx >= 0 && gx < W_IMG)
                v = xb[(size_t)(c0 + c) * (H_IMG * W_IMG) + gy * W_IMG + gx];
            xs[c * (6 * XROW) + r * XROW + col + 4 * (col >> 5)] = v;
        }
        // stage duplicated weight pairs (float2 copies, coalesced)
        {
            const float2* wsrc = (const float2*)(g_wt2 + (size_t)c0 * 9 * PCH * 2);
            float2* wdst = (float2*)wsd;
            for (int k = tid; k < (CC * 9 * PCH); k += 128) wdst[k] = wsrc[k];
        }
        __syncthreads();

#pragma unroll
        for (int c = 0; c < CC; c++) {
#pragma unroll
            for (int ky = 0; ky < 3; ky++) {
                const float* row = xs + c * (6 * XROW) + (ty + ky) * XROW;
                float v[10];
#pragma unroll
                for (int j = 0; j < 10; j++) v[j] = row[off[j]];
                unsigned long long pe[5], po[4];
#pragma unroll
                for (int m = 0; m < 5; m++) pe[m] = pack2(v[2 * m], v[2 * m + 1]);
#pragma unroll
                for (int m = 0; m < 4; m++) po[m] = pack2(v[2 * m + 1], v[2 * m + 2]);

                const unsigned long long* wrow =
                    (const unsigned long long*)(wsd + ((c * 9 + ky * 3) * PCH) * 2);
#pragma unroll
                for (int kx = 0; kx < 3; kx++) {
                    unsigned long long wp[7];
#pragma unroll
                    for (int i = 0; i < 7; i++)
                        wp[i] = wrow[kx * PCH + tp * 7 + i];   // broadcast LDS.64 of (w,w)
#pragma unroll
                    for (int i = 0; i < 7; i++) {
#pragma unroll
                        for (int m = 0; m < 4; m++) {
                            unsigned long long xv = (kx == 0) ? pe[m] : (kx == 1) ? po[m] : pe[m + 1];
                            ffma2(acc[i][m], wp[i], xv);
                        }
                    }
                }
            }
        }
    }

    // ---- epilogue: ReLU -> swizzled relu buffer (conflict-free) ----
    __syncthreads();   // all warps done reading xs/wsd before overwrite
    {
        const int q0 = 5 * (tx + 8 * ty);   // = 5*(pix>>3) for this thread's pixels
#pragma unroll
        for (int i = 0; i < 7; i++) {
            int q = tp * 7 + i;
            int col = (q + q0) & 31;
#pragma unroll
            for (int m = 0; m < 4; m++) {
                float a, bb;
                unpack2(acc[i][m], a, bb);
                a  = fmaxf(a, 0.f);
                bb = fmaxf(bb, 0.f);
                int pix = ty * 64 + tx * 8 + 2 * m;
                buf[pix * 32 + col]       = a;
                buf[(pix + 1) * 32 + col] = bb;
            }
        }
    }
    __syncthreads();

    // ---- fused 1x1 conv2 + store feat2 ----
    {
        const int pb = ty * 64 + tx * 8;
        const int q0 = 5 * (tx + 8 * ty);
        float o[7][8];
#pragma unroll
        for (int i = 0; i < 7; i++)
#pragma unroll
            for (int k = 0; k < 8; k++) o[i][k] = 0.f;

#pragma unroll 4
        for (int q = 0; q < PCH; q++) {
            int col = (q + q0) & 31;
            float r[8];
#pragma unroll
            for (int k = 0; k < 8; k++) r[k] = buf[(pb + k) * 32 + col];
#pragma unroll
            for (int i = 0; i < 7; i++) {
                float w = w2s[(tp * 7 + i) * PCH + q];
#pragma unroll
                for (int k = 0; k < 8; k++) o[i][k] = fmaf(w, r[k], o[i][k]);
            }
        }

        int px = x0 + tx * 8;
#pragma unroll
        for (int i = 0; i < 7; i++) {
            int pout = tp * 7 + i;
            float* dst = g_feat2 + (((size_t)b * PCH + pout) * H_IMG + (y0 + ty)) * W_IMG + px;
#pragma unroll
            for (int k = 0; k < 8; k++)
                if (px + k < W_IMG) dst[k] = o[i][k];
        }
    }
}

// ---------- rotated position-sensitive sampling: one warp per box ----------
__global__ void sample_kernel(const float* __restrict__ boxes, float* __restrict__ out) {
    int gwarp = (blockIdx.x * blockDim.x + threadIdx.x) >> 5;
    int lane  = threadIdx.x & 31;
    if (gwarp >= BATCH * NBOX) return;
    int b = gwarp >> 11;
    int n = gwarp & (NBOX - 1);
    const float* bx = boxes + (size_t)(b * NBOX + n) * 7;

    float val = 0.f;
    if (lane < PCH) {
        float xg = bx[0], yg = bx[1], wg = bx[3], lg = bx[4], rg = bx[6];
        int i = lane / 7;
        int j = lane - i * 7;
        float lx = (float)i * (1.f / 3.f) - 0.5f;
        float ly = (float)j * (1.f / 6.f) - 0.5f;
        float xx = lx * wg;
        float yy = ly * lg;
        float sT, cT;
        sincosf(rg, &sT, &cT);
        float gx = (xx * cT + yy * sT + xg) * 2.5f;
        float gy = (yy * cT - xx * sT + yg + 40.f) * 2.5f;

        const float* img = g_feat2 + ((size_t)b * PCH + lane) * (H_IMG * W_IMG);
        float xf = floorf(gx), yf = floorf(gy);
        int xi = (int)xf, yi = (int)yf;
        float fx = gx - xf, fy = gy - yf;
        float Ia = 0.f, Ib = 0.f, Ic = 0.f, Id = 0.f;
        bool vx0 = (xi >= 0) && (xi <= W_IMG - 1);
        bool vx1 = (xi + 1 >= 0) && (xi + 1 <= W_IMG - 1);
        bool vy0 = (yi >= 0) && (yi <= H_IMG - 1);
        bool vy1 = (yi + 1 >= 0) && (yi + 1 <= H_IMG - 1);
        if (vy0 && vx0) Ia = img[yi * W_IMG + xi];
        if (vy1 && vx0) Ib = img[(yi + 1) * W_IMG + xi];
        if (vy0 && vx1) Ic = img[yi * W_IMG + xi + 1];
        if (vy1 && vx1) Id = img[(yi + 1) * W_IMG + xi + 1];
        val = (1.f - fx) * (1.f - fy) * Ia + (1.f - fx) * fy * Ib
            + fx * (1.f - fy) * Ic + fx * fy * Id;
    }
#pragma unroll
    for (int off = 16; off; off >>= 1)
        val += __shfl_xor_sync(0xffffffffu, val, off);
    if (lane == 0) out[b * NBOX + n] = val * (1.f / 28.f);
}

// ---------- launch ----------
extern "C" void kernel_launch(void* const* d_in, const int* in_sizes, int n_in,
                              void* d_out, int out_size) {
    const float* x     = (const float*)d_in[0];
    const float* boxes = (const float*)d_in[1];
    const float* w1    = (const float*)d_in[2];
    const float* gamma = (const float*)d_in[3];
    const float* beta  = (const float*)d_in[4];
    const float* mean  = (const float*)d_in[5];
    const float* var   = (const float*)d_in[6];
    const float* w2    = (const float*)d_in[7];
    float* out = (float*)d_out;

    prep_kernel<<<252, 256>>>(w1, gamma, beta, mean, var);

    dim3 grid((W_IMG + TILE_X - 1) / TILE_X, H_IMG / TILE_Y, BATCH);  // (3, 50, 4)
    conv_kernel<<<grid, 128>>>(x, w2);

    sample_kernel<<<(BATCH * NBOX * 32) / 256, 256>>>(boxes, out);
}

// round 8
// speedup vs baseline: 2.7436x; 2.4157x over previous
#include <cuda_runtime.h>
#include <cuda_bf16.h>
#include <cstdint>

// ---------------- problem constants ----------------
#define H_IMG 200
#define W_IMG 176
#define CIN   256
#define PCH   28
#define BATCH 4
#define NBOX  2048
#define HW    (H_IMG*W_IMG)

#define TW    64     // CTA tile width (pixels)
#define TH    2      // CTA tile height
#define CBLK  16     // input channels per k-step
#define NCB   (CIN/CBLK)   // 16

// ---------------- smem layout (bytes, dynamic) ----------------
// x halo: 4 rows x 66 cols, cell = 16 bf16 (32B) padded to 48B
#define CELL      48
#define XROWS     4
#define XCOLS     66
#define XBYTES    (XROWS*XCOLS*CELL)       // 12672
#define SM_XHI    0
#define SM_XLO    (SM_XHI + XBYTES)        // 12672
#define SM_B      (SM_XLO + XBYTES)        // 25344 ; B: 576 rows x 48B = 27648
#define SM_W2     (SM_B + 576*CELL)        // 52992 ; 784 floats
#define SM_SHIFT  (SM_W2 + 3136)           // 56128 ; 28 floats
#define SM_TOTAL  (SM_SHIFT + 128)         // 56256
// D exchange reuses [SM_XHI ..): 128 px x 33 f32 = 16896 B

// ---------------- device scratch ----------------
__device__ float g_feat2[(size_t)BATCH * PCH * HW];
// weights: [cb16][tap9][part2][n32][k16] bf16  (part0=hi, part1=lo)
__device__ __align__(16) __nv_bfloat16 g_wB[NCB * 9 * 2 * 32 * CBLK];
__device__ float g_shift[PCH];

// ---------------- helpers ----------------
__device__ __forceinline__ uint32_t smem_u32(const void* p) {
    uint32_t a;
    asm("{ .reg .u64 t; cvta.to.shared.u64 t, %1; cvt.u32.u64 %0, t; }" : "=r"(a) : "l"(p));
    return a;
}

__device__ __forceinline__ void ldmatrix_x4(uint32_t& r0, uint32_t& r1, uint32_t& r2, uint32_t& r3,
                                            uint32_t addr) {
    asm volatile("ldmatrix.sync.aligned.m8n8.x4.shared.b16 {%0,%1,%2,%3}, [%4];"
                 : "=r"(r0), "=r"(r1), "=r"(r2), "=r"(r3) : "r"(addr));
}

__device__ __forceinline__ void mma_bf16(float& d0, float& d1, float& d2, float& d3,
                                         uint32_t a0, uint32_t a1, uint32_t a2, uint32_t a3,
                                         uint32_t b0, uint32_t b1) {
    asm volatile(
        "mma.sync.aligned.m16n8k16.row.col.f32.bf16.bf16.f32 "
        "{%0,%1,%2,%3}, {%4,%5,%6,%7}, {%8,%9}, {%0,%1,%2,%3};"
        : "+f"(d0), "+f"(d1), "+f"(d2), "+f"(d3)
        : "r"(a0), "r"(a1), "r"(a2), "r"(a3), "r"(b0), "r"(b1));
}

__device__ __forceinline__ void split_hl(float v, uint16_t& h, uint16_t& l) {
    __nv_bfloat16 hb = __float2bfloat16_rn(v);
    __nv_bfloat16 lb = __float2bfloat16_rn(v - __bfloat162float(hb));
    h = __bfloat16_as_ushort(hb);
    l = __bfloat16_as_ushort(lb);
}

// ---------------- prep: BN fold + bf16 hi/lo weight layout ----------------
__global__ void prep_kernel(const float* __restrict__ w1,
                            const float* __restrict__ gamma,
                            const float* __restrict__ beta,
                            const float* __restrict__ mean,
                            const float* __restrict__ var) {
    int idx = blockIdx.x * blockDim.x + threadIdx.x;
    if (idx < PCH) {
        float inv = gamma[idx] * rsqrtf(var[idx] + 1e-3f);
        g_shift[idx] = beta[idx] - mean[idx] * inv;
    }
    // total = 16*9*2*32*16 = 147456
    if (idx < NCB * 9 * 2 * 32 * CBLK) {
        int k = idx & 15;
        int tmp = idx >> 4;
        int n = tmp & 31; tmp >>= 5;
        int part = tmp & 1; tmp >>= 1;
        int t = tmp % 9;
        int cb = tmp / 9;
        float w = 0.f;
        if (n < PCH) {
            float sc = gamma[n] * rsqrtf(var[n] + 1e-3f);
            w = w1[((size_t)n * CIN + (cb * CBLK + k)) * 9 + t] * sc;
        }
        uint16_t h, l;
        split_hl(w, h, l);
        g_wB[idx] = __ushort_as_bfloat16(part == 0 ? h : l);
    }
}

// ---------------- fused conv1+BN+ReLU+conv2 (mma.sync bf16 hi/lo) ----------------
__global__ __launch_bounds__(256, 3)
void conv_kernel(const float* __restrict__ x, const float* __restrict__ w2) {
    extern __shared__ __align__(16) char smem[];
    const int tid  = threadIdx.x;
    const int wid  = tid >> 5;
    const int lane = tid & 31;
    const int x0 = blockIdx.x * TW;
    const int y0 = blockIdx.y * TH;
    const int b  = blockIdx.z;

    const uint32_t s_xhi = smem_u32(smem) + SM_XHI;
    const uint32_t s_xlo = smem_u32(smem) + SM_XLO;
    const uint32_t s_b   = smem_u32(smem) + SM_B;
    float* w2s = (float*)(smem + SM_W2);
    float* shs = (float*)(smem + SM_SHIFT);
    uint32_t* bsm = (uint32_t*)(smem + SM_B);
    uint16_t* xh16 = (uint16_t*)(smem + SM_XHI);
    uint16_t* xl16 = (uint16_t*)(smem + SM_XLO);

    for (int k = tid; k < PCH * PCH; k += 256) w2s[k] = w2[k];
    if (tid < PCH) shs[tid] = g_shift[tid];

    // warp tile: ry in {0,1}, px0 in {0,16,32,48}
    const int ry  = wid >> 2;
    const int px0 = (wid & 3) * 16;
    const int g   = lane >> 2;          // mma row group
    const int c2  = (lane & 3) * 2;     // mma col pair

    // D accumulators: 4 n-tiles x 4 f32
    float d[4][4];
#pragma unroll
    for (int i = 0; i < 4; i++)
#pragma unroll
        for (int j = 0; j < 4; j++) d[i][j] = 0.f;

    const float* xb = x + (size_t)b * CIN * HW;
    const uint32_t* wsrc = (const uint32_t*)g_wB;

    // per-lane ldmatrix address components
    const int a_pix   = lane & 15;            // A row (pixel within warp tile)
    const int a_khalf = lane >> 4;            // A k-half
    const int b_n     = ((lane >> 4) << 3) + (lane & 7);   // B n within 16-pair
    const int b_khalf = (lane >> 3) & 1;

    for (int cb = 0; cb < NCB; cb++) {
        __syncthreads();
        // ---- stage B for this cb: 4608 u32, row(8 u32) -> padded row of 12 u32 ----
        {
            const uint32_t* src = wsrc + cb * 4608;
            for (int u = tid; u < 4608; u += 256)
                bsm[(u >> 3) * 12 + (u & 7)] = src[u];
        }
        // ---- stage x halo: 4 x 66 x 8 chan-pairs, hi/lo split ----
        for (int u = tid; u < XROWS * XCOLS * 8; u += 256) {
            int ch2 = u / (XROWS * XCOLS);
            int rem = u - ch2 * (XROWS * XCOLS);
            int r = rem / XCOLS;
            int c = rem - r * XCOLS;
            int gy = y0 - 1 + r;
            int gx = x0 - 1 + c;
            float v0 = 0.f, v1 = 0.f;
            if (gy >= 0 && gy < H_IMG && gx >= 0 && gx < W_IMG) {
                const float* p = xb + (size_t)(cb * CBLK + 2 * ch2) * HW + gy * W_IMG + gx;
                v0 = p[0];
                v1 = p[HW];
            }
            uint16_t h0, l0, h1, l1;
            split_hl(v0, h0, l0);
            split_hl(v1, h1, l1);
            int cell = (r * XCOLS + c) * (CELL / 2);   // in u16 units
            xh16[cell + 2 * ch2]     = h0;
            xh16[cell + 2 * ch2 + 1] = h1;
            xl16[cell + 2 * ch2]     = l0;
            xl16[cell + 2 * ch2 + 1] = l1;
        }
        __syncthreads();

#pragma unroll
        for (int t = 0; t < 9; t++) {
            const int dy = t / 3, dx = t - 3 * dy;
            // A fragments (hi, lo)
            uint32_t aoff = (uint32_t)(((ry + dy) * XCOLS + px0 + dx + a_pix) * CELL + a_khalf * 16);
            uint32_t ah0, ah1, ah2, ah3, al0, al1, al2, al3;
            ldmatrix_x4(ah0, ah1, ah2, ah3, s_xhi + aoff);
            ldmatrix_x4(al0, al1, al2, al3, s_xlo + aoff);

#pragma unroll
            for (int ntp = 0; ntp < 2; ntp++) {
                uint32_t brow_hi = (uint32_t)(((t * 2 + 0) * 32 + ntp * 16 + b_n) * CELL + b_khalf * 16);
                uint32_t brow_lo = (uint32_t)(((t * 2 + 1) * 32 + ntp * 16 + b_n) * CELL + b_khalf * 16);
                uint32_t bh0, bh1, bh2, bh3, bl0, bl1, bl2, bl3;
                ldmatrix_x4(bh0, bh1, bh2, bh3, s_b + brow_hi);
                ldmatrix_x4(bl0, bl1, bl2, bl3, s_b + brow_lo);

                float* d0 = d[ntp * 2];
                float* d1 = d[ntp * 2 + 1];
                // n-tile 0 of pair
                mma_bf16(d0[0], d0[1], d0[2], d0[3], ah0, ah1, ah2, ah3, bh0, bh1); // Ah*Bh
                mma_bf16(d0[0], d0[1], d0[2], d0[3], ah0, ah1, ah2, ah3, bl0, bl1); // Ah*Bl
                mma_bf16(d0[0], d0[1], d0[2], d0[3], al0, al1, al2, al3, bh0, bh1); // Al*Bh
                // n-tile 1 of pair
                mma_bf16(d1[0], d1[1], d1[2], d1[3], ah0, ah1, ah2, ah3, bh2, bh3);
                mma_bf16(d1[0], d1[1], d1[2], d1[3], ah0, ah1, ah2, ah3, bl2, bl3);
                mma_bf16(d1[0], d1[1], d1[2], d1[3], al0, al1, al2, al3, bh2, bh3);
            }
        }
    }

    // ---- exchange D through smem (stride 33 => conflict-free) ----
    __syncthreads();
    float* sD = (float*)(smem + SM_XHI);
    {
        const int pixbase = ry * TW + px0;
#pragma unroll
        for (int nt = 0; nt < 4; nt++) {
            int n = nt * 8 + c2;
            sD[(pixbase + g) * 33 + n]       = d[nt][0];
            sD[(pixbase + g) * 33 + n + 1]   = d[nt][1];
            sD[(pixbase + g + 8) * 33 + n]     = d[nt][2];
            sD[(pixbase + g + 8) * 33 + n + 1] = d[nt][3];
        }
    }
    __syncthreads();

    // ---- BN shift + ReLU + conv2(1x1) + store ----
    {
        const int pix  = tid >> 1;       // 0..127
        const int half = tid & 1;        // output channels [half*14, +14)
        float rl[PCH];
#pragma unroll
        for (int q = 0; q < PCH; q++)
            rl[q] = fmaxf(sD[pix * 33 + q] + shs[q], 0.f);

        int px = x0 + (pix & 63);
        int py = y0 + (pix >> 6);
        if (px < W_IMG) {
#pragma unroll
            for (int i = 0; i < 14; i++) {
                int p = half * 14 + i;
                float o = 0.f;
#pragma unroll
                for (int q = 0; q < PCH; q++)
                    o = fmaf(w2s[p * PCH + q], rl[q], o);
                g_feat2[((size_t)b * PCH + p) * HW + py * W_IMG + px] = o;
            }
        }
    }
}

// ---------------- rotated position-sensitive sampling: one warp per box ----------------
__global__ void sample_kernel(const float* __restrict__ boxes, float* __restrict__ out) {
    int gwarp = (blockIdx.x * blockDim.x + threadIdx.x) >> 5;
    int lane  = threadIdx.x & 31;
    if (gwarp >= BATCH * NBOX) return;
    int b = gwarp >> 11;
    int n = gwarp & (NBOX - 1);
    const float* bx = boxes + (size_t)(b * NBOX + n) * 7;

    float val = 0.f;
    if (lane < PCH) {
        float xg = bx[0], yg = bx[1], wg = bx[3], lg = bx[4], rg = bx[6];
        int i = lane / 7;
        int j = lane - i * 7;
        float lx = (float)i * (1.f / 3.f) - 0.5f;
        float ly = (float)j * (1.f / 6.f) - 0.5f;
        float xx = lx * wg;
        float yy = ly * lg;
        float sT, cT;
        sincosf(rg, &sT, &cT);
        float gx = (xx * cT + yy * sT + xg) * 2.5f;
        float gy = (yy * cT - xx * sT + yg + 40.f) * 2.5f;

        const float* img = g_feat2 + ((size_t)b * PCH + lane) * HW;
        float xf = floorf(gx), yf = floorf(gy);
        int xi = (int)xf, yi = (int)yf;
        float fx = gx - xf, fy = gy - yf;
        float Ia = 0.f, Ib = 0.f, Ic = 0.f, Id = 0.f;
        bool vx0 = (xi >= 0) && (xi <= W_IMG - 1);
        bool vx1 = (xi + 1 >= 0) && (xi + 1 <= W_IMG - 1);
        bool vy0 = (yi >= 0) && (yi <= H_IMG - 1);
        bool vy1 = (yi + 1 >= 0) && (yi + 1 <= H_IMG - 1);
        if (vy0 && vx0) Ia = img[yi * W_IMG + xi];
        if (vy1 && vx0) Ib = img[(yi + 1) * W_IMG + xi];
        if (vy0 && vx1) Ic = img[yi * W_IMG + xi + 1];
        if (vy1 && vx1) Id = img[(yi + 1) * W_IMG + xi + 1];
        val = (1.f - fx) * (1.f - fy) * Ia + (1.f - fx) * fy * Ib
            + fx * (1.f - fy) * Ic + fx * fy * Id;
    }
#pragma unroll
    for (int off = 16; off; off >>= 1)
        val += __shfl_xor_sync(0xffffffffu, val, off);
    if (lane == 0) out[b * NBOX + n] = val * (1.f / 28.f);
}

// ---------------- launch ----------------
extern "C" void kernel_launch(void* const* d_in, const int* in_sizes, int n_in,
                              void* d_out, int out_size) {
    const float* x     = (const float*)d_in[0];
    const float* boxes = (const float*)d_in[1];
    const float* w1    = (const float*)d_in[2];
    const float* gamma = (const float*)d_in[3];
    const float* beta  = (const float*)d_in[4];
    const float* mean  = (const float*)d_in[5];
    const float* var   = (const float*)d_in[6];
    const float* w2    = (const float*)d_in[7];
    float* out = (float*)d_out;

    cudaFuncSetAttribute(conv_kernel, cudaFuncAttributeMaxDynamicSharedMemorySize, SM_TOTAL);

    prep_kernel<<<576, 256>>>(w1, gamma, beta, mean, var);

    dim3 grid((W_IMG + TW - 1) / TW, H_IMG / TH, BATCH);   // (3, 100, 4) = 1200 CTAs
    conv_kernel<<<grid, 256, SM_TOTAL>>>(x, w2);

    sample_kernel<<<(BATCH * NBOX * 32) / 256, 256>>>(boxes, out);
}

// round 9
// speedup vs baseline: 3.0389x; 1.1077x over previous
#include <cuda_runtime.h>
#include <cuda_bf16.h>
#include <cstdint>

// ---------------- problem constants ----------------
#define H_IMG 200
#define W_IMG 176
#define CIN   256
#define PCH   28
#define BATCH 4
#define NBOX  2048
#define HW    (H_IMG*W_IMG)

#define TW    64     // CTA tile width (pixels)
#define TH    2      // CTA tile height
#define CBLK  16     // input channels per k-step
#define NCB   (CIN/CBLK)   // 16

// ---------------- smem layout (bytes, dynamic) ----------------
#define CELL      48
#define XROWS     4
#define XCOLS     66
#define XBYTES    (XROWS*XCOLS*CELL)       // 12672
#define SM_XHI    0
#define SM_XLO    (SM_XHI + XBYTES)        // 12672
#define SM_B      (SM_XLO + XBYTES)        // 25344 ; B: 576 rows x 48B
#define SM_W2     (SM_B + 576*CELL)        // 52992
#define SM_SHIFT  (SM_W2 + 3136)           // 56128
#define SM_TOTAL  (SM_SHIFT + 128)         // 56256

#define NXIT 9       // max x staging iters per thread (2112/256)
#define NBIT 18      // B staging iters per thread (4608/256)

// ---------------- device scratch ----------------
__device__ float g_feat2[(size_t)BATCH * PCH * HW];
__device__ __align__(16) __nv_bfloat16 g_wB[NCB * 9 * 2 * 32 * CBLK];
__device__ float g_shift[PCH];

// ---------------- helpers ----------------
__device__ __forceinline__ uint32_t smem_u32(const void* p) {
    uint32_t a;
    asm("{ .reg .u64 t; cvta.to.shared.u64 t, %1; cvt.u32.u64 %0, t; }" : "=r"(a) : "l"(p));
    return a;
}
__device__ __forceinline__ void ldmatrix_x4(uint32_t& r0, uint32_t& r1, uint32_t& r2, uint32_t& r3,
                                            uint32_t addr) {
    asm volatile("ldmatrix.sync.aligned.m8n8.x4.shared.b16 {%0,%1,%2,%3}, [%4];"
                 : "=r"(r0), "=r"(r1), "=r"(r2), "=r"(r3) : "r"(addr));
}
__device__ __forceinline__ void mma_bf16(float& d0, float& d1, float& d2, float& d3,
                                         uint32_t a0, uint32_t a1, uint32_t a2, uint32_t a3,
                                         uint32_t b0, uint32_t b1) {
    asm volatile(
        "mma.sync.aligned.m16n8k16.row.col.f32.bf16.bf16.f32 "
        "{%0,%1,%2,%3}, {%4,%5,%6,%7}, {%8,%9}, {%0,%1,%2,%3};"
        : "+f"(d0), "+f"(d1), "+f"(d2), "+f"(d3)
        : "r"(a0), "r"(a1), "r"(a2), "r"(a3), "r"(b0), "r"(b1));
}

// ---------------- prep: BN fold + bf16 hi/lo weight layout (RN split) ----------------
__global__ void prep_kernel(const float* __restrict__ w1,
                            const float* __restrict__ gamma,
                            const float* __restrict__ beta,
                            const float* __restrict__ mean,
                            const float* __restrict__ var) {
    int idx = blockIdx.x * blockDim.x + threadIdx.x;
    if (idx < PCH) {
        float inv = gamma[idx] * rsqrtf(var[idx] + 1e-3f);
        g_shift[idx] = beta[idx] - mean[idx] * inv;
    }
    if (idx < NCB * 9 * 2 * 32 * CBLK) {
        int k = idx & 15;
        int tmp = idx >> 4;
        int n = tmp & 31; tmp >>= 5;
        int part = tmp & 1; tmp >>= 1;
        int t = tmp % 9;
        int cb = tmp / 9;
        float w = 0.f;
        if (n < PCH) {
            float sc = gamma[n] * rsqrtf(var[n] + 1e-3f);
            w = w1[((size_t)n * CIN + (cb * CBLK + k)) * 9 + t] * sc;
        }
        __nv_bfloat16 hb = __float2bfloat16_rn(w);
        __nv_bfloat16 lb = __float2bfloat16_rn(w - __bfloat162float(hb));
        g_wB[idx] = (part == 0) ? hb : lb;
    }
}

// ---------------- fused conv1+BN+ReLU+conv2 (mma.sync, reg-pipelined staging) ----------------
__global__ __launch_bounds__(256, 3)
void conv_kernel(const float* __restrict__ x, const float* __restrict__ w2) {
    extern __shared__ __align__(16) char smem[];
    const int tid  = threadIdx.x;
    const int wid  = tid >> 5;
    const int lane = tid & 31;
    const int x0 = blockIdx.x * TW;
    const int y0 = blockIdx.y * TH;
    const int b  = blockIdx.z;

    const uint32_t s_xhi = smem_u32(smem) + SM_XHI;
    const uint32_t s_xlo = smem_u32(smem) + SM_XLO;
    const uint32_t s_b   = smem_u32(smem) + SM_B;
    float* w2s = (float*)(smem + SM_W2);
    float* shs = (float*)(smem + SM_SHIFT);
    uint32_t* bsm  = (uint32_t*)(smem + SM_B);
    uint32_t* xh32 = (uint32_t*)(smem + SM_XHI);
    uint32_t* xl32 = (uint32_t*)(smem + SM_XLO);

    for (int k = tid; k < PCH * PCH; k += 256) w2s[k] = w2[k];
    if (tid < PCH) shs[tid] = g_shift[tid];

    // warp tile: ry in {0,1}, px0 in {0,16,32,48}
    const int ry  = wid >> 2;
    const int px0 = (wid & 3) * 16;
    const int g   = lane >> 2;
    const int c2  = (lane & 3) * 2;

    float d[4][4];
#pragma unroll
    for (int i = 0; i < 4; i++)
#pragma unroll
        for (int j = 0; j < 4; j++) d[i][j] = 0.f;

    const float* xb = x + (size_t)b * CIN * HW;
    const uint32_t* wsrc = (const uint32_t*)g_wB;

    const int a_pix   = lane & 15;
    const int a_khalf = lane >> 4;
    const int b_n     = ((lane >> 4) << 3) + (lane & 7);
    const int b_khalf = (lane >> 3) & 1;

    // ---- register prefetch buffers ----
    float xv0[NXIT], xv1[NXIT];

    // prefetch for cb = 0
    {
        const float* base = xb;
#pragma unroll
        for (int i = 0; i < NXIT; i++) {
            int u = tid + i * 256;
            xv0[i] = 0.f; xv1[i] = 0.f;
            if (u < XROWS * XCOLS * 8) {
                int ch2 = u / (XROWS * XCOLS);
                int rem = u - ch2 * (XROWS * XCOLS);
                int r = rem / XCOLS;
                int c = rem - r * XCOLS;
                int gy = y0 - 1 + r, gx = x0 - 1 + c;
                if (gy >= 0 && gy < H_IMG && gx >= 0 && gx < W_IMG) {
                    const float* p = base + (size_t)(2 * ch2) * HW + gy * W_IMG + gx;
                    xv0[i] = p[0];
                    xv1[i] = p[HW];
                }
            }
        }
    }

    for (int cb = 0; cb < NCB; cb++) {
        __syncthreads();     // previous MMA phase done reading smem

        // ---- store phase: B LDG first (latency hides under x convert) ----
        {
            const uint32_t* srcB = wsrc + cb * 4608;
            uint32_t bw[NBIT];
#pragma unroll
            for (int i = 0; i < NBIT; i++) bw[i] = srcB[tid + i * 256];

            // x: convert prefetched regs -> smem (RZ hi + RN lo, packed stores)
#pragma unroll
            for (int i = 0; i < NXIT; i++) {
                int u = tid + i * 256;
                if (u < XROWS * XCOLS * 8) {
                    int ch2 = u / (XROWS * XCOLS);
                    int rem = u - ch2 * (XROWS * XCOLS);
                    int r = rem / XCOLS;
                    int c = rem - r * XCOLS;
                    uint32_t u0 = __float_as_uint(xv0[i]);
                    uint32_t u1 = __float_as_uint(xv1[i]);
                    uint32_t hp;
                    asm("prmt.b32 %0, %1, %2, 0x7632;" : "=r"(hp) : "r"(u0), "r"(u1));
                    float h0 = __uint_as_float(u0 & 0xffff0000u);
                    float h1 = __uint_as_float(u1 & 0xffff0000u);
                    float l0 = xv0[i] - h0;
                    float l1 = xv1[i] - h1;
                    uint32_t lp;
                    asm("cvt.rn.bf16x2.f32 %0, %1, %2;" : "=r"(lp) : "f"(l1), "f"(l0));
                    int si = (r * XCOLS + c) * 12 + ch2;
                    xh32[si] = hp;
                    xl32[si] = lp;
                }
            }
#pragma unroll
            for (int i = 0; i < NBIT; i++) {
                int u = tid + i * 256;
                bsm[(u >> 3) * 12 + (u & 7)] = bw[i];
            }
        }
        __syncthreads();

        // ---- prefetch x for cb+1 (LDGs fly during MMA phase) ----
        if (cb + 1 < NCB) {
            const float* base = xb + (size_t)(cb + 1) * CBLK * HW;
#pragma unroll
            for (int i = 0; i < NXIT; i++) {
                int u = tid + i * 256;
                xv0[i] = 0.f; xv1[i] = 0.f;
                if (u < XROWS * XCOLS * 8) {
                    int ch2 = u / (XROWS * XCOLS);
                    int rem = u - ch2 * (XROWS * XCOLS);
                    int r = rem / XCOLS;
                    int c = rem - r * XCOLS;
                    int gy = y0 - 1 + r, gx = x0 - 1 + c;
                    if (gy >= 0 && gy < H_IMG && gx >= 0 && gx < W_IMG) {
                        const float* p = base + (size_t)(2 * ch2) * HW + gy * W_IMG + gx;
                        xv0[i] = p[0];
                        xv1[i] = p[HW];
                    }
                }
            }
        }

        // ---- MMA phase: 9 taps ----
#pragma unroll
        for (int t = 0; t < 9; t++) {
            const int dy = t / 3, dx = t - 3 * dy;
            uint32_t aoff = (uint32_t)(((ry + dy) * XCOLS + px0 + dx + a_pix) * CELL + a_khalf * 16);
            uint32_t ah0, ah1, ah2, ah3, al0, al1, al2, al3;
            ldmatrix_x4(ah0, ah1, ah2, ah3, s_xhi + aoff);
            ldmatrix_x4(al0, al1, al2, al3, s_xlo + aoff);

#pragma unroll
            for (int ntp = 0; ntp < 2; ntp++) {
                uint32_t brow_hi = (uint32_t)(((t * 2 + 0) * 32 + ntp * 16 + b_n) * CELL + b_khalf * 16);
                uint32_t brow_lo = (uint32_t)(((t * 2 + 1) * 32 + ntp * 16 + b_n) * CELL + b_khalf * 16);
                uint32_t bh0, bh1, bh2, bh3, bl0, bl1, bl2, bl3;
                ldmatrix_x4(bh0, bh1, bh2, bh3, s_b + brow_hi);
                ldmatrix_x4(bl0, bl1, bl2, bl3, s_b + brow_lo);

                float* d0 = d[ntp * 2];
                float* d1 = d[ntp * 2 + 1];
                mma_bf16(d0[0], d0[1], d0[2], d0[3], ah0, ah1, ah2, ah3, bh0, bh1);
                mma_bf16(d1[0], d1[1], d1[2], d1[3], ah0, ah1, ah2, ah3, bh2, bh3);
                mma_bf16(d0[0], d0[1], d0[2], d0[3], ah0, ah1, ah2, ah3, bl0, bl1);
                mma_bf16(d1[0], d1[1], d1[2], d1[3], ah0, ah1, ah2, ah3, bl2, bl3);
                mma_bf16(d0[0], d0[1], d0[2], d0[3], al0, al1, al2, al3, bh0, bh1);
                mma_bf16(d1[0], d1[1], d1[2], d1[3], al0, al1, al2, al3, bh2, bh3);
            }
        }
    }

    // ---- exchange D through smem (stride 33 => conflict-free) ----
    __syncthreads();
    float* sD = (float*)(smem + SM_XHI);
    {
        const int pixbase = ry * TW + px0;
#pragma unroll
        for (int nt = 0; nt < 4; nt++) {
            int n = nt * 8 + c2;
            sD[(pixbase + g) * 33 + n]         = d[nt][0];
            sD[(pixbase + g) * 33 + n + 1]     = d[nt][1];
            sD[(pixbase + g + 8) * 33 + n]     = d[nt][2];
            sD[(pixbase + g + 8) * 33 + n + 1] = d[nt][3];
        }
    }
    __syncthreads();

    // ---- BN shift + ReLU + conv2(1x1) + store ----
    {
        const int pix  = tid >> 1;
        const int half = tid & 1;
        float rl[PCH];
#pragma unroll
        for (int q = 0; q < PCH; q++)
            rl[q] = fmaxf(sD[pix * 33 + q] + shs[q], 0.f);

        int px = x0 + (pix & 63);
        int py = y0 + (pix >> 6);
        if (px < W_IMG) {
#pragma unroll
            for (int i = 0; i < 14; i++) {
                int p = half * 14 + i;
                float o = 0.f;
#pragma unroll
                for (int q = 0; q < PCH; q++)
                    o = fmaf(w2s[p * PCH + q], rl[q], o);
                g_feat2[((size_t)b * PCH + p) * HW + py * W_IMG + px] = o;
            }
        }
    }
}

// ---------------- rotated position-sensitive sampling: one warp per box ----------------
__global__ void sample_kernel(const float* __restrict__ boxes, float* __restrict__ out) {
    int gwarp = (blockIdx.x * blockDim.x + threadIdx.x) >> 5;
    int lane  = threadIdx.x & 31;
    if (gwarp >= BATCH * NBOX) return;
    int b = gwarp >> 11;
    int n = gwarp & (NBOX - 1);
    const float* bx = boxes + (size_t)(b * NBOX + n) * 7;

    float val = 0.f;
    if (lane < PCH) {
        float xg = bx[0], yg = bx[1], wg = bx[3], lg = bx[4], rg = bx[6];
        int i = lane / 7;
        int j = lane - i * 7;
        float lx = (float)i * (1.f / 3.f) - 0.5f;
        float ly = (float)j * (1.f / 6.f) - 0.5f;
        float xx = lx * wg;
        float yy = ly * lg;
        float sT, cT;
        sincosf(rg, &sT, &cT);
        float gx = (xx * cT + yy * sT + xg) * 2.5f;
        float gy = (yy * cT - xx * sT + yg + 40.f) * 2.5f;

        const float* img = g_feat2 + ((size_t)b * PCH + lane) * HW;
        float xf = floorf(gx), yf = floorf(gy);
        int xi = (int)xf, yi = (int)yf;
        float fx = gx - xf, fy = gy - yf;
        float Ia = 0.f, Ib = 0.f, Ic = 0.f, Id = 0.f;
        bool vx0 = (xi >= 0) && (xi <= W_IMG - 1);
        bool vx1 = (xi + 1 >= 0) && (xi + 1 <= W_IMG - 1);
        bool vy0 = (yi >= 0) && (yi <= H_IMG - 1);
        bool vy1 = (yi + 1 >= 0) && (yi + 1 <= H_IMG - 1);
        if (vy0 && vx0) Ia = img[yi * W_IMG + xi];
        if (vy1 && vx0) Ib = img[(yi + 1) * W_IMG + xi];
        if (vy0 && vx1) Ic = img[yi * W_IMG + xi + 1];
        if (vy1 && vx1) Id = img[(yi + 1) * W_IMG + xi + 1];
        val = (1.f - fx) * (1.f - fy) * Ia + (1.f - fx) * fy * Ib
            + fx * (1.f - fy) * Ic + fx * fy * Id;
    }
#pragma unroll
    for (int off = 16; off; off >>= 1)
        val += __shfl_xor_sync(0xffffffffu, val, off);
    if (lane == 0) out[b * NBOX + n] = val * (1.f / 28.f);
}

// ---------------- launch ----------------
extern "C" void kernel_launch(void* const* d_in, const int* in_sizes, int n_in,
                              void* d_out, int out_size) {
    const float* x     = (const float*)d_in[0];
    const float* boxes = (const float*)d_in[1];
    const float* w1    = (const float*)d_in[2];
    const float* gamma = (const float*)d_in[3];
    const float* beta  = (const float*)d_in[4];
    const float* mean  = (const float*)d_in[5];
    const float* var   = (const float*)d_in[6];
    const float* w2    = (const float*)d_in[7];
    float* out = (float*)d_out;

    cudaFuncSetAttribute(conv_kernel, cudaFuncAttributeMaxDynamicSharedMemorySize, SM_TOTAL);

    prep_kernel<<<576, 256>>>(w1, gamma, beta, mean, var);

    dim3 grid((W_IMG + TW - 1) / TW, H_IMG / TH, BATCH);   // (3, 100, 4) = 1200 CTAs
    conv_kernel<<<grid, 256, SM_TOTAL>>>(x, w2);

    sample_kernel<<<(BATCH * NBOX * 32) / 256, 256>>>(boxes, out);
}

// round 10
// speedup vs baseline: 3.7628x; 1.2382x over previous
#include <cuda_runtime.h>
#include <cuda_bf16.h>
#include <cstdint>

// ---------------- problem constants ----------------
#define H_IMG 200
#define W_IMG 176
#define CIN   256
#define PCH   28
#define BATCH 4
#define NBOX  2048
#define HW    (H_IMG*W_IMG)

#define TW    64     // CTA tile width (pixels)
#define TH    4      // CTA tile height
#define CBLK  16     // input channels per k-step
#define NCB   (CIN/CBLK)   // 16

// ---------------- smem layout (bytes, dynamic) ----------------
#define CELL      48
#define XROWS     6
#define XCOLS     66
#define XBYTES    (XROWS*XCOLS*CELL)       // 19008
#define BBYTES    (576*CELL)               // 27648 per buffer
#define SM_XHI    0
#define SM_XLO    (SM_XHI + XBYTES)        // 19008
#define SM_B      (SM_XLO + XBYTES)        // 38016 ; 2 buffers
#define SM_W2     (SM_B + 2*BBYTES)        // 93312
#define SM_SHIFT  (SM_W2 + 3136)           // 96448
#define SM_TOTAL  (SM_SHIFT + 128)         // 96576

#define XITEMS (XROWS*XCOLS*8)             // 3168
#define NXIT   13                          // ceil(3168/256)

// ---------------- device scratch ----------------
__device__ float g_feat2[(size_t)BATCH * PCH * HW];
__device__ __align__(16) __nv_bfloat16 g_wB[NCB * 9 * 2 * 32 * CBLK];
__device__ float g_shift[PCH];

// ---------------- helpers ----------------
__device__ __forceinline__ uint32_t smem_u32(const void* p) {
    uint32_t a;
    asm("{ .reg .u64 t; cvta.to.shared.u64 t, %1; cvt.u32.u64 %0, t; }" : "=r"(a) : "l"(p));
    return a;
}
__device__ __forceinline__ void ldmatrix_x4(uint32_t& r0, uint32_t& r1, uint32_t& r2, uint32_t& r3,
                                            uint32_t addr) {
    asm volatile("ldmatrix.sync.aligned.m8n8.x4.shared.b16 {%0,%1,%2,%3}, [%4];"
                 : "=r"(r0), "=r"(r1), "=r"(r2), "=r"(r3) : "r"(addr));
}
__device__ __forceinline__ void mma_bf16(float& d0, float& d1, float& d2, float& d3,
                                         uint32_t a0, uint32_t a1, uint32_t a2, uint32_t a3,
                                         uint32_t b0, uint32_t b1) {
    asm volatile(
        "mma.sync.aligned.m16n8k16.row.col.f32.bf16.bf16.f32 "
        "{%0,%1,%2,%3}, {%4,%5,%6,%7}, {%8,%9}, {%0,%1,%2,%3};"
        : "+f"(d0), "+f"(d1), "+f"(d2), "+f"(d3)
        : "r"(a0), "r"(a1), "r"(a2), "r"(a3), "r"(b0), "r"(b1));
}
__device__ __forceinline__ void cp_async16(uint32_t dst, const void* src) {
    asm volatile("cp.async.ca.shared.global [%0], [%1], 16;" :: "r"(dst), "l"(src));
}
#define CP_COMMIT() asm volatile("cp.async.commit_group;" ::: "memory")
#define CP_WAIT0()  asm volatile("cp.async.wait_group 0;" ::: "memory")

// ---------------- prep: BN fold + bf16 hi/lo weight layout ----------------
__global__ void prep_kernel(const float* __restrict__ w1,
                            const float* __restrict__ gamma,
                            const float* __restrict__ beta,
                            const float* __restrict__ mean,
                            const float* __restrict__ var) {
    int idx = blockIdx.x * blockDim.x + threadIdx.x;
    if (idx < PCH) {
        float inv = gamma[idx] * rsqrtf(var[idx] + 1e-3f);
        g_shift[idx] = beta[idx] - mean[idx] * inv;
    }
    if (idx < NCB * 9 * 2 * 32 * CBLK) {
        int k = idx & 15;
        int tmp = idx >> 4;
        int n = tmp & 31; tmp >>= 5;
        int part = tmp & 1; tmp >>= 1;
        int t = tmp % 9;
        int cb = tmp / 9;
        float w = 0.f;
        if (n < PCH) {
            float sc = gamma[n] * rsqrtf(var[n] + 1e-3f);
            w = w1[((size_t)n * CIN + (cb * CBLK + k)) * 9 + t] * sc;
        }
        __nv_bfloat16 hb = __float2bfloat16_rn(w);
        __nv_bfloat16 lb = __float2bfloat16_rn(w - __bfloat162float(hb));
        g_wB[idx] = (part == 0) ? hb : lb;
    }
}

// ---------------- fused conv1+BN+ReLU+conv2 ----------------
__global__ __launch_bounds__(256, 2)
void conv_kernel(const float* __restrict__ x, const float* __restrict__ w2) {
    extern __shared__ __align__(16) char smem[];
    const int tid  = threadIdx.x;
    const int wid  = tid >> 5;
    const int lane = tid & 31;
    const int x0 = blockIdx.x * TW;
    const int y0 = blockIdx.y * TH;
    const int b  = blockIdx.z;

    const uint32_t s_xhi = smem_u32(smem) + SM_XHI;
    const uint32_t s_xlo = smem_u32(smem) + SM_XLO;
    const uint32_t s_b0  = smem_u32(smem) + SM_B;
    float* w2s = (float*)(smem + SM_W2);
    float* shs = (float*)(smem + SM_SHIFT);
    uint32_t* xh32 = (uint32_t*)(smem + SM_XHI);
    uint32_t* xl32 = (uint32_t*)(smem + SM_XLO);

    for (int k = tid; k < PCH * PCH; k += 256) w2s[k] = w2[k];
    if (tid < PCH) shs[tid] = g_shift[tid];

    // warp tile: row ry = wid&3, 32 px starting at px0 = (wid>>2)*32
    const int ry  = wid & 3;
    const int px0 = (wid >> 2) * 32;
    const int g   = lane >> 2;
    const int c2  = (lane & 3) * 2;

    float d[2][4][4];
#pragma unroll
    for (int m = 0; m < 2; m++)
#pragma unroll
        for (int i = 0; i < 4; i++)
#pragma unroll
            for (int j = 0; j < 4; j++) d[m][i][j] = 0.f;

    const float* xb = x + (size_t)b * CIN * HW;
    const char* wsrc = (const char*)g_wB;

    const int a_pix   = lane & 15;
    const int a_khalf = lane >> 4;
    const int b_n     = ((lane >> 4) << 3) + (lane & 7);
    const int b_khalf = (lane >> 3) & 1;

    // ---- B(0) via cp.async into buffer 0 ----
    {
#pragma unroll
        for (int i = 0; i < 5; i++) {
            int u = tid + i * 256;
            if (u < 1152)
                cp_async16(s_b0 + (u >> 1) * CELL + (u & 1) * 16, wsrc + u * 16);
        }
        CP_COMMIT();
    }

    // ---- x(0) register prefetch ----
    float xv0[NXIT], xv1[NXIT];
    {
#pragma unroll
        for (int i = 0; i < NXIT; i++) {
            int u = tid + i * 256;
            xv0[i] = 0.f; xv1[i] = 0.f;
            if (u < XITEMS) {
                int ch2 = u / (XROWS * XCOLS);
                int rem = u - ch2 * (XROWS * XCOLS);
                int r = rem / XCOLS;
                int c = rem - r * XCOLS;
                int gy = y0 - 1 + r, gx = x0 - 1 + c;
                if (gy >= 0 && gy < H_IMG && gx >= 0 && gx < W_IMG) {
                    const float* p = xb + (size_t)(2 * ch2) * HW + gy * W_IMG + gx;
                    xv0[i] = p[0];
                    xv1[i] = p[HW];
                }
            }
        }
    }

    for (int cb = 0; cb < NCB; cb++) {
        __syncthreads();     // previous MMA phase done reading smem

        // ---- issue B(cb+1) cp.async into the other buffer ----
        if (cb + 1 < NCB) {
            uint32_t dstb = s_b0 + ((cb + 1) & 1) * BBYTES;
            const char* srcb = wsrc + (size_t)(cb + 1) * 18432;
#pragma unroll
            for (int i = 0; i < 5; i++) {
                int u = tid + i * 256;
                if (u < 1152)
                    cp_async16(dstb + (u >> 1) * CELL + (u & 1) * 16, srcb + u * 16);
            }
        }
        CP_COMMIT();

        // ---- convert prefetched x regs -> smem ----
#pragma unroll
        for (int i = 0; i < NXIT; i++) {
            int u = tid + i * 256;
            if (u < XITEMS) {
                int ch2 = u / (XROWS * XCOLS);
                int rem = u - ch2 * (XROWS * XCOLS);
                int r = rem / XCOLS;
                int c = rem - r * XCOLS;
                uint32_t u0 = __float_as_uint(xv0[i]);
                uint32_t u1 = __float_as_uint(xv1[i]);
                uint32_t hp;
                asm("prmt.b32 %0, %1, %2, 0x7632;" : "=r"(hp) : "r"(u0), "r"(u1));
                float h0 = __uint_as_float(u0 & 0xffff0000u);
                float h1 = __uint_as_float(u1 & 0xffff0000u);
                float l0 = xv0[i] - h0;
                float l1 = xv1[i] - h1;
                uint32_t lp;
                asm("cvt.rn.bf16x2.f32 %0, %1, %2;" : "=r"(lp) : "f"(l1), "f"(l0));
                int si = (r * XCOLS + c) * 12 + ch2;
                xh32[si] = hp;
                xl32[si] = lp;
            }
        }
        CP_WAIT0();          // B(cb+1) (and B(0) on first iter) landed
        __syncthreads();

        // ---- prefetch x(cb+1) (LDGs fly during MMA phase) ----
        if (cb + 1 < NCB) {
            const float* base = xb + (size_t)(cb + 1) * CBLK * HW;
#pragma unroll
            for (int i = 0; i < NXIT; i++) {
                int u = tid + i * 256;
                xv0[i] = 0.f; xv1[i] = 0.f;
                if (u < XITEMS) {
                    int ch2 = u / (XROWS * XCOLS);
                    int rem = u - ch2 * (XROWS * XCOLS);
                    int r = rem / XCOLS;
                    int c = rem - r * XCOLS;
                    int gy = y0 - 1 + r, gx = x0 - 1 + c;
                    if (gy >= 0 && gy < H_IMG && gx >= 0 && gx < W_IMG) {
                        const float* p = base + (size_t)(2 * ch2) * HW + gy * W_IMG + gx;
                        xv0[i] = p[0];
                        xv1[i] = p[HW];
                    }
                }
            }
        }

        // ---- MMA phase: 9 taps, 2 M-tiles per warp ----
        const uint32_t s_b = s_b0 + (cb & 1) * BBYTES;
#pragma unroll
        for (int t = 0; t < 9; t++) {
            const int dy = t / 3, dx = t - 3 * dy;
            uint32_t ah[2][4], al[2][4];
#pragma unroll
            for (int m = 0; m < 2; m++) {
                uint32_t aoff = (uint32_t)(((ry + dy) * XCOLS + px0 + m * 16 + dx + a_pix) * CELL
                                           + a_khalf * 16);
                ldmatrix_x4(ah[m][0], ah[m][1], ah[m][2], ah[m][3], s_xhi + aoff);
                ldmatrix_x4(al[m][0], al[m][1], al[m][2], al[m][3], s_xlo + aoff);
            }
#pragma unroll
            for (int ntp = 0; ntp < 2; ntp++) {
                uint32_t brow_hi = (uint32_t)(((t * 2 + 0) * 32 + ntp * 16 + b_n) * CELL + b_khalf * 16);
                uint32_t brow_lo = (uint32_t)(((t * 2 + 1) * 32 + ntp * 16 + b_n) * CELL + b_khalf * 16);
                uint32_t bh0, bh1, bh2, bh3, bl0, bl1, bl2, bl3;
                ldmatrix_x4(bh0, bh1, bh2, bh3, s_b + brow_hi);
                ldmatrix_x4(bl0, bl1, bl2, bl3, s_b + brow_lo);
#pragma unroll
                for (int m = 0; m < 2; m++) {
                    float* d0 = d[m][ntp * 2];
                    float* d1 = d[m][ntp * 2 + 1];
                    mma_bf16(d0[0], d0[1], d0[2], d0[3], ah[m][0], ah[m][1], ah[m][2], ah[m][3], bh0, bh1);
                    mma_bf16(d1[0], d1[1], d1[2], d1[3], ah[m][0], ah[m][1], ah[m][2], ah[m][3], bh2, bh3);
                    mma_bf16(d0[0], d0[1], d0[2], d0[3], ah[m][0], ah[m][1], ah[m][2], ah[m][3], bl0, bl1);
                    mma_bf16(d1[0], d1[1], d1[2], d1[3], ah[m][0], ah[m][1], ah[m][2], ah[m][3], bl2, bl3);
                    mma_bf16(d0[0], d0[1], d0[2], d0[3], al[m][0], al[m][1], al[m][2], al[m][3], bh0, bh1);
                    mma_bf16(d1[0], d1[1], d1[2], d1[3], al[m][0], al[m][1], al[m][2], al[m][3], bh2, bh3);
                }
            }
        }
    }

    // ---- exchange D through smem (stride 33 => conflict-free) ----
    __syncthreads();
    float* sD = (float*)(smem + SM_XHI);
#pragma unroll
    for (int m = 0; m < 2; m++) {
        const int pixbase = ry * TW + px0 + m * 16;
#pragma unroll
        for (int nt = 0; nt < 4; nt++) {
            int n = nt * 8 + c2;
            sD[(pixbase + g) * 33 + n]         = d[m][nt][0];
            sD[(pixbase + g) * 33 + n + 1]     = d[m][nt][1];
            sD[(pixbase + g + 8) * 33 + n]     = d[m][nt][2];
            sD[(pixbase + g + 8) * 33 + n + 1] = d[m][nt][3];
        }
    }
    __syncthreads();

    // ---- BN shift + ReLU + conv2(1x1) + store: 1 pixel per thread ----
    {
        const int pix = tid;
        float rl[PCH];
#pragma unroll
        for (int q = 0; q < PCH; q++)
            rl[q] = fmaxf(sD[pix * 33 + q] + shs[q], 0.f);

        int px = x0 + (pix & 63);
        int py = y0 + (pix >> 6);
        if (px < W_IMG) {
#pragma unroll 4
            for (int p = 0; p < PCH; p++) {
                float o = 0.f;
#pragma unroll
                for (int q = 0; q < PCH; q++)
                    o = fmaf(w2s[p * PCH + q], rl[q], o);
                g_feat2[((size_t)b * PCH + p) * HW + py * W_IMG + px] = o;
            }
        }
    }
}

// ---------------- rotated position-sensitive sampling: one warp per box ----------------
__global__ void sample_kernel(const float* __restrict__ boxes, float* __restrict__ out) {
    int gwarp = (blockIdx.x * blockDim.x + threadIdx.x) >> 5;
    int lane  = threadIdx.x & 31;
    if (gwarp >= BATCH * NBOX) return;
    int b = gwarp >> 11;
    int n = gwarp & (NBOX - 1);
    const float* bx = boxes + (size_t)(b * NBOX + n) * 7;

    float val = 0.f;
    if (lane < PCH) {
        float xg = bx[0], yg = bx[1], wg = bx[3], lg = bx[4], rg = bx[6];
        int i = lane / 7;
        int j = lane - i * 7;
        float lx = (float)i * (1.f / 3.f) - 0.5f;
        float ly = (float)j * (1.f / 6.f) - 0.5f;
        float xx = lx * wg;
        float yy = ly * lg;
        float sT, cT;
        sincosf(rg, &sT, &cT);
        float gx = (xx * cT + yy * sT + xg) * 2.5f;
        float gy = (yy * cT - xx * sT + yg + 40.f) * 2.5f;

        const float* img = g_feat2 + ((size_t)b * PCH + lane) * HW;
        float xf = floorf(gx), yf = floorf(gy);
        int xi = (int)xf, yi = (int)yf;
        float fx = gx - xf, fy = gy - yf;
        float Ia = 0.f, Ib = 0.f, Ic = 0.f, Id = 0.f;
        bool vx0 = (xi >= 0) && (xi <= W_IMG - 1);
        bool vx1 = (xi + 1 >= 0) && (xi + 1 <= W_IMG - 1);
        bool vy0 = (yi >= 0) && (yi <= H_IMG - 1);
        bool vy1 = (yi + 1 >= 0) && (yi + 1 <= H_IMG - 1);
        if (vy0 && vx0) Ia = img[yi * W_IMG + xi];
        if (vy1 && vx0) Ib = img[(yi + 1) * W_IMG + xi];
        if (vy0 && vx1) Ic = img[yi * W_IMG + xi + 1];
        if (vy1 && vx1) Id = img[(yi + 1) * W_IMG + xi + 1];
        val = (1.f - fx) * (1.f - fy) * Ia + (1.f - fx) * fy * Ib
            + fx * (1.f - fy) * Ic + fx * fy * Id;
    }
#pragma unroll
    for (int off = 16; off; off >>= 1)
        val += __shfl_xor_sync(0xffffffffu, val, off);
    if (lane == 0) out[b * NBOX + n] = val * (1.f / 28.f);
}

// ---------------- launch ----------------
extern "C" void kernel_launch(void* const* d_in, const int* in_sizes, int n_in,
                              void* d_out, int out_size) {
    const float* x     = (const float*)d_in[0];
    const float* boxes = (const float*)d_in[1];
    const float* w1    = (const float*)d_in[2];
    const float* gamma = (const float*)d_in[3];
    const float* beta  = (const float*)d_in[4];
    const float* mean  = (const float*)d_in[5];
    const float* var   = (const float*)d_in[6];
    const float* w2    = (const float*)d_in[7];
    float* out = (float*)d_out;

    cudaFuncSetAttribute(conv_kernel, cudaFuncAttributeMaxDynamicSharedMemorySize, SM_TOTAL);

    prep_kernel<<<576, 256>>>(w1, gamma, beta, mean, var);

    dim3 grid((W_IMG + TW - 1) / TW, H_IMG / TH, BATCH);   // (3, 50, 4) = 600 CTAs
    conv_kernel<<<grid, 256, SM_TOTAL>>>(x, w2);

    sample_kernel<<<(BATCH * NBOX * 32) / 256, 256>>>(boxes, out);
}

// round 11
// speedup vs baseline: 5.1690x; 1.3737x over previous
#include <cuda_runtime.h>
#include <cuda_fp16.h>
#include <cstdint>

// ---------------- problem constants ----------------
#define H_IMG 200
#define W_IMG 176
#define CIN   256
#define PCH   28
#define BATCH 4
#define NBOX  2048
#define HW    (H_IMG*W_IMG)

#define TW    64     // CTA tile width (pixels)
#define TH    4      // CTA tile height
#define CBLK  16     // input channels per k-step
#define NCB   (CIN/CBLK)   // 16

// ---------------- smem layout (bytes, dynamic) ----------------
#define CELL      48
#define XROWS     6
#define XCOLS     66
#define XBYTES    (XROWS*XCOLS*CELL)       // 19008 (single fp16 x buffer)
#define BBYTES    (576*CELL)               // 27648 per buffer (wh+wl rows)
#define SM_XH     0
#define SM_B      (SM_XH + XBYTES)         // 19008 ; 2 buffers
#define SM_W2     (SM_B + 2*BBYTES)        // 74304
#define SM_SHIFT  (SM_W2 + 3136)           // 77440
#define SM_TOTAL  (SM_SHIFT + 128)         // 77568
// D exchange (256 px x 33 f32 = 33792 B) reuses smem after final sync

#define XITEMS (XROWS*XCOLS*8)             // 3168 channel-pairs
#define NXIT   13                          // ceil(3168/256)

// ---------------- device scratch ----------------
__device__ float g_feat2[(size_t)BATCH * PCH * HW];
// weights: [cb16][tap9][part2][n32][k16] fp16  (part0=hi, part1=lo)
__device__ __align__(16) __half g_wB[NCB * 9 * 2 * 32 * CBLK];
__device__ float g_shift[PCH];

// ---------------- helpers ----------------
__device__ __forceinline__ uint32_t smem_u32(const void* p) {
    uint32_t a;
    asm("{ .reg .u64 t; cvta.to.shared.u64 t, %1; cvt.u32.u64 %0, t; }" : "=r"(a) : "l"(p));
    return a;
}
__device__ __forceinline__ void ldmatrix_x4(uint32_t& r0, uint32_t& r1, uint32_t& r2, uint32_t& r3,
                                            uint32_t addr) {
    asm volatile("ldmatrix.sync.aligned.m8n8.x4.shared.b16 {%0,%1,%2,%3}, [%4];"
                 : "=r"(r0), "=r"(r1), "=r"(r2), "=r"(r3) : "r"(addr));
}
__device__ __forceinline__ void mma_fp16(float& d0, float& d1, float& d2, float& d3,
                                         uint32_t a0, uint32_t a1, uint32_t a2, uint32_t a3,
                                         uint32_t b0, uint32_t b1) {
    asm volatile(
        "mma.sync.aligned.m16n8k16.row.col.f32.f16.f16.f32 "
        "{%0,%1,%2,%3}, {%4,%5,%6,%7}, {%8,%9}, {%0,%1,%2,%3};"
        : "+f"(d0), "+f"(d1), "+f"(d2), "+f"(d3)
        : "r"(a0), "r"(a1), "r"(a2), "r"(a3), "r"(b0), "r"(b1));
}
__device__ __forceinline__ void cp_async16(uint32_t dst, const void* src) {
    asm volatile("cp.async.ca.shared.global [%0], [%1], 16;" :: "r"(dst), "l"(src));
}
#define CP_COMMIT() asm volatile("cp.async.commit_group;" ::: "memory")
#define CP_WAIT0()  asm volatile("cp.async.wait_group 0;" ::: "memory")

// ---------------- prep: BN fold + fp16 hi/lo weight layout ----------------
__global__ void prep_kernel(const float* __restrict__ w1,
                            const float* __restrict__ gamma,
                            const float* __restrict__ beta,
                            const float* __restrict__ mean,
                            const float* __restrict__ var) {
    int idx = blockIdx.x * blockDim.x + threadIdx.x;
    if (idx < PCH) {
        float inv = gamma[idx] * rsqrtf(var[idx] + 1e-3f);
        g_shift[idx] = beta[idx] - mean[idx] * inv;
    }
    if (idx < NCB * 9 * 2 * 32 * CBLK) {
        int k = idx & 15;
        int tmp = idx >> 4;
        int n = tmp & 31; tmp >>= 5;
        int part = tmp & 1; tmp >>= 1;
        int t = tmp % 9;
        int cb = tmp / 9;
        float w = 0.f;
        if (n < PCH) {
            float sc = gamma[n] * rsqrtf(var[n] + 1e-3f);
            w = w1[((size_t)n * CIN + (cb * CBLK + k)) * 9 + t] * sc;
        }
        __half hb = __float2half_rn(w);
        __half lb = __float2half_rn(w - __half2float(hb));
        g_wB[idx] = (part == 0) ? hb : lb;
    }
}

// ---------------- fused conv1+BN+ReLU+conv2 (fp16 2-term mma.sync) ----------------
__global__ __launch_bounds__(256, 2)
void conv_kernel(const float* __restrict__ x, const float* __restrict__ w2) {
    extern __shared__ __align__(16) char smem[];
    const int tid  = threadIdx.x;
    const int wid  = tid >> 5;
    const int lane = tid & 31;
    const int x0 = blockIdx.x * TW;
    const int y0 = blockIdx.y * TH;
    const int b  = blockIdx.z;

    const uint32_t s_xh = smem_u32(smem) + SM_XH;
    const uint32_t s_b0 = smem_u32(smem) + SM_B;
    float* w2s = (float*)(smem + SM_W2);
    float* shs = (float*)(smem + SM_SHIFT);
    uint32_t* xh32 = (uint32_t*)(smem + SM_XH);

    for (int k = tid; k < PCH * PCH; k += 256) w2s[k] = w2[k];
    if (tid < PCH) shs[tid] = g_shift[tid];

    // warp tile: row ry = wid&3, 32 px starting at px0 = (wid>>2)*32
    const int ry  = wid & 3;
    const int px0 = (wid >> 2) * 32;
    const int g   = lane >> 2;
    const int c2  = (lane & 3) * 2;

    float d[2][4][4];
#pragma unroll
    for (int m = 0; m < 2; m++)
#pragma unroll
        for (int i = 0; i < 4; i++)
#pragma unroll
            for (int j = 0; j < 4; j++) d[m][i][j] = 0.f;

    const float* xb = x + (size_t)b * CIN * HW;
    const char* wsrc = (const char*)g_wB;

    const int a_pix   = lane & 15;
    const int a_khalf = lane >> 4;
    const int b_n     = ((lane >> 4) << 3) + (lane & 7);
    const int b_khalf = (lane >> 3) & 1;

    // ---- B(0) via cp.async into buffer 0 ----
    {
#pragma unroll
        for (int i = 0; i < 5; i++) {
            int u = tid + i * 256;
            if (u < 1152)
                cp_async16(s_b0 + (u >> 1) * CELL + (u & 1) * 16, wsrc + u * 16);
        }
        CP_COMMIT();
    }

    // ---- x(0) register prefetch ----
    float xv0[NXIT], xv1[NXIT];
    {
#pragma unroll
        for (int i = 0; i < NXIT; i++) {
            int u = tid + i * 256;
            xv0[i] = 0.f; xv1[i] = 0.f;
            if (u < XITEMS) {
                int ch2 = u / (XROWS * XCOLS);
                int rem = u - ch2 * (XROWS * XCOLS);
                int r = rem / XCOLS;
                int c = rem - r * XCOLS;
                int gy = y0 - 1 + r, gx = x0 - 1 + c;
                if (gy >= 0 && gy < H_IMG && gx >= 0 && gx < W_IMG) {
                    const float* p = xb + (size_t)(2 * ch2) * HW + gy * W_IMG + gx;
                    xv0[i] = p[0];
                    xv1[i] = p[HW];
                }
            }
        }
    }

    for (int cb = 0; cb < NCB; cb++) {
        __syncthreads();     // previous MMA phase done reading smem

        // ---- issue B(cb+1) cp.async into the other buffer ----
        if (cb + 1 < NCB) {
            uint32_t dstb = s_b0 + ((cb + 1) & 1) * BBYTES;
            const char* srcb = wsrc + (size_t)(cb + 1) * 18432;
#pragma unroll
            for (int i = 0; i < 5; i++) {
                int u = tid + i * 256;
                if (u < 1152)
                    cp_async16(dstb + (u >> 1) * CELL + (u & 1) * 16, srcb + u * 16);
            }
        }
        CP_COMMIT();

        // ---- convert prefetched x regs -> fp16 smem (single buffer) ----
#pragma unroll
        for (int i = 0; i < NXIT; i++) {
            int u = tid + i * 256;
            if (u < XITEMS) {
                int ch2 = u / (XROWS * XCOLS);
                int rem = u - ch2 * (XROWS * XCOLS);
                int r = rem / XCOLS;
                int c = rem - r * XCOLS;
                uint32_t hp;
                asm("cvt.rn.f16x2.f32 %0, %1, %2;" : "=r"(hp) : "f"(xv1[i]), "f"(xv0[i]));
                xh32[(r * XCOLS + c) * 12 + ch2] = hp;
            }
        }
        CP_WAIT0();          // B landed
        __syncthreads();

        // ---- prefetch x(cb+1) (LDGs fly during MMA phase) ----
        if (cb + 1 < NCB) {
            const float* base = xb + (size_t)(cb + 1) * CBLK * HW;
#pragma unroll
            for (int i = 0; i < NXIT; i++) {
                int u = tid + i * 256;
                xv0[i] = 0.f; xv1[i] = 0.f;
                if (u < XITEMS) {
                    int ch2 = u / (XROWS * XCOLS);
                    int rem = u - ch2 * (XROWS * XCOLS);
                    int r = rem / XCOLS;
                    int c = rem - r * XCOLS;
                    int gy = y0 - 1 + r, gx = x0 - 1 + c;
                    if (gy >= 0 && gy < H_IMG && gx >= 0 && gx < W_IMG) {
                        const float* p = base + (size_t)(2 * ch2) * HW + gy * W_IMG + gx;
                        xv0[i] = p[0];
                        xv1[i] = p[HW];
                    }
                }
            }
        }

        // ---- MMA phase: 9 taps, 2 M-tiles per warp, 2-term (Ah*Bh + Ah*Bl) ----
        const uint32_t s_b = s_b0 + (cb & 1) * BBYTES;
#pragma unroll
        for (int t = 0; t < 9; t++) {
            const int dy = t / 3, dx = t - 3 * dy;
            uint32_t ah[2][4];
#pragma unroll
            for (int m = 0; m < 2; m++) {
                uint32_t aoff = (uint32_t)(((ry + dy) * XCOLS + px0 + m * 16 + dx + a_pix) * CELL
                                           + a_khalf * 16);
                ldmatrix_x4(ah[m][0], ah[m][1], ah[m][2], ah[m][3], s_xh + aoff);
            }
#pragma unroll
            for (int ntp = 0; ntp < 2; ntp++) {
                uint32_t brow_hi = (uint32_t)(((t * 2 + 0) * 32 + ntp * 16 + b_n) * CELL + b_khalf * 16);
                uint32_t brow_lo = (uint32_t)(((t * 2 + 1) * 32 + ntp * 16 + b_n) * CELL + b_khalf * 16);
                uint32_t bh0, bh1, bh2, bh3, bl0, bl1, bl2, bl3;
                ldmatrix_x4(bh0, bh1, bh2, bh3, s_b + brow_hi);
                ldmatrix_x4(bl0, bl1, bl2, bl3, s_b + brow_lo);
#pragma unroll
                for (int m = 0; m < 2; m++) {
                    float* d0 = d[m][ntp * 2];
                    float* d1 = d[m][ntp * 2 + 1];
                    mma_fp16(d0[0], d0[1], d0[2], d0[3], ah[m][0], ah[m][1], ah[m][2], ah[m][3], bh0, bh1);
                    mma_fp16(d1[0], d1[1], d1[2], d1[3], ah[m][0], ah[m][1], ah[m][2], ah[m][3], bh2, bh3);
                    mma_fp16(d0[0], d0[1], d0[2], d0[3], ah[m][0], ah[m][1], ah[m][2], ah[m][3], bl0, bl1);
                    mma_fp16(d1[0], d1[1], d1[2], d1[3], ah[m][0], ah[m][1], ah[m][2], ah[m][3], bl2, bl3);
                }
            }
        }
    }

    // ---- exchange D through smem (stride 33 => conflict-free) ----
    __syncthreads();
    float* sD = (float*)(smem + SM_XH);
#pragma unroll
    for (int m = 0; m < 2; m++) {
        const int pixbase = ry * TW + px0 + m * 16;
#pragma unroll
        for (int nt = 0; nt < 4; nt++) {
            int n = nt * 8 + c2;
            sD[(pixbase + g) * 33 + n]         = d[m][nt][0];
            sD[(pixbase + g) * 33 + n + 1]     = d[m][nt][1];
            sD[(pixbase + g + 8) * 33 + n]     = d[m][nt][2];
            sD[(pixbase + g + 8) * 33 + n + 1] = d[m][nt][3];
        }
    }
    __syncthreads();

    // ---- BN shift + ReLU + conv2(1x1) + store: 1 pixel per thread ----
    {
        const int pix = tid;
        float rl[PCH];
#pragma unroll
        for (int q = 0; q < PCH; q++)
            rl[q] = fmaxf(sD[pix * 33 + q] + shs[q], 0.f);

        int px = x0 + (pix & 63);
        int py = y0 + (pix >> 6);
        if (px < W_IMG) {
#pragma unroll 4
            for (int p = 0; p < PCH; p++) {
                float o = 0.f;
#pragma unroll
                for (int q = 0; q < PCH; q++)
                    o = fmaf(w2s[p * PCH + q], rl[q], o);
                g_feat2[((size_t)b * PCH + p) * HW + py * W_IMG + px] = o;
            }
        }
    }
}

// ---------------- rotated position-sensitive sampling: one warp per box ----------------
__global__ void sample_kernel(const float* __restrict__ boxes, float* __restrict__ out) {
    int gwarp = (blockIdx.x * blockDim.x + threadIdx.x) >> 5;
    int lane  = threadIdx.x & 31;
    if (gwarp >= BATCH * NBOX) return;
    int b = gwarp >> 11;
    int n = gwarp & (NBOX - 1);
    const float* bx = boxes + (size_t)(b * NBOX + n) * 7;

    float val = 0.f;
    if (lane < PCH) {
        float xg = bx[0], yg = bx[1], wg = bx[3], lg = bx[4], rg = bx[6];
        int i = lane / 7;
        int j = lane - i * 7;
        float lx = (float)i * (1.f / 3.f) - 0.5f;
        float ly = (float)j * (1.f / 6.f) - 0.5f;
        float xx = lx * wg;
        float yy = ly * lg;
        float sT, cT;
        sincosf(rg, &sT, &cT);
        float gx = (xx * cT + yy * sT + xg) * 2.5f;
        float gy = (yy * cT - xx * sT + yg + 40.f) * 2.5f;

        const float* img = g_feat2 + ((size_t)b * PCH + lane) * HW;
        float xf = floorf(gx), yf = floorf(gy);
        int xi = (int)xf, yi = (int)yf;
        float fx = gx - xf, fy = gy - yf;
        float Ia = 0.f, Ib = 0.f, Ic = 0.f, Id = 0.f;
        bool vx0 = (xi >= 0) && (xi <= W_IMG - 1);
        bool vx1 = (xi + 1 >= 0) && (xi + 1 <= W_IMG - 1);
        bool vy0 = (yi >= 0) && (yi <= H_IMG - 1);
        bool vy1 = (yi + 1 >= 0) && (yi + 1 <= H_IMG - 1);
        if (vy0 && vx0) Ia = img[yi * W_IMG + xi];
        if (vy1 && vx0) Ib = img[(yi + 1) * W_IMG + xi];
        if (vy0 && vx1) Ic = img[yi * W_IMG + xi + 1];
        if (vy1 && vx1) Id = img[(yi + 1) * W_IMG + xi + 1];
        val = (1.f - fx) * (1.f - fy) * Ia + (1.f - fx) * fy * Ib
            + fx * (1.f - fy) * Ic + fx * fy * Id;
    }
#pragma unroll
    for (int off = 16; off; off >>= 1)
        val += __shfl_xor_sync(0xffffffffu, val, off);
    if (lane == 0) out[b * NBOX + n] = val * (1.f / 28.f);
}

// ---------------- launch ----------------
extern "C" void kernel_launch(void* const* d_in, const int* in_sizes, int n_in,
                              void* d_out, int out_size) {
    const float* x     = (const float*)d_in[0];
    const float* boxes = (const float*)d_in[1];
    const float* w1    = (const float*)d_in[2];
    const float* gamma = (const float*)d_in[3];
    const float* beta  = (const float*)d_in[4];
    const float* mean  = (const float*)d_in[5];
    const float* var   = (const float*)d_in[6];
    const float* w2    = (const float*)d_in[7];
    float* out = (float*)d_out;

    cudaFuncSetAttribute(conv_kernel, cudaFuncAttributeMaxDynamicSharedMemorySize, SM_TOTAL);

    prep_kernel<<<576, 256>>>(w1, gamma, beta, mean, var);

    dim3 grid((W_IMG + TW - 1) / TW, H_IMG / TH, BATCH);   // (3, 50, 4) = 600 CTAs
    conv_kernel<<<grid, 256, SM_TOTAL>>>(x, w2);

    sample_kernel<<<(BATCH * NBOX * 32) / 256, 256>>>(boxes, out);
}